// round 16
// baseline (speedup 1.0000x reference)
#include <cuda_runtime.h>
#include <cuda_fp16.h>
#include <math.h>
#include <stdint.h>

#define TT 256
#define BB 64
#define HH 1024
#define G4 4096
#define MM (TT*BB)
#define NCT 128           // CTAs in persistent step kernel

// ---------------------------------------------------------------------------
// Scratch (device globals: allocation-free per harness rules)
// ---------------------------------------------------------------------------
__device__ float g_xg[(size_t)MM * G4];
__device__ float g_out5[(size_t)MM * HH];
__device__ __half g_h[2][BB * HH];          // ping-pong hidden (single fp16)
__device__ __half g_ahi[(size_t)MM * HH];
__device__ __half g_alo[(size_t)MM * HH];
__device__ __half g_w5[(size_t)G4 * HH];    // w_ih5 fp16
__device__ __half g_w6[(size_t)G4 * HH];    // w_ih6 fp16
__device__ __half g_u5[(size_t)G4 * HH];    // w_hh5 fp16
__device__ __half g_u6[(size_t)G4 * HH];    // w_hh6 fp16
__device__ int g_ctr[2 * TT];

// ---------------------------------------------------------------------------
// mma.sync helpers
// ---------------------------------------------------------------------------
__device__ __forceinline__ uint32_t smem_u32(const void* p) {
    uint32_t a;
    asm("{ .reg .u64 t; cvta.to.shared.u64 t, %1; cvt.u32.u64 %0, t; }"
        : "=r"(a) : "l"(p));
    return a;
}
__device__ __forceinline__ void ldsm4(uint32_t* r, uint32_t addr) {
    asm volatile("ldmatrix.sync.aligned.m8n8.x4.shared.b16 {%0,%1,%2,%3}, [%4];"
                 : "=r"(r[0]), "=r"(r[1]), "=r"(r[2]), "=r"(r[3]) : "r"(addr));
}
__device__ __forceinline__ void ldsm2(uint32_t* r, uint32_t addr) {
    asm volatile("ldmatrix.sync.aligned.m8n8.x2.shared.b16 {%0,%1}, [%2];"
                 : "=r"(r[0]), "=r"(r[1]) : "r"(addr));
}
// fp16 inputs, fp32 accumulate
__device__ __forceinline__ void mma16816(float* d, const uint32_t* a,
                                         const uint32_t* b) {
    asm volatile(
        "mma.sync.aligned.m16n8k16.row.col.f32.f16.f16.f32 "
        "{%0,%1,%2,%3}, {%4,%5,%6,%7}, {%8,%9}, {%0,%1,%2,%3};"
        : "+f"(d[0]), "+f"(d[1]), "+f"(d[2]), "+f"(d[3])
        : "r"(a[0]), "r"(a[1]), "r"(a[2]), "r"(a[3]), "r"(b[0]), "r"(b[1]));
}
// fp16 inputs, fp16 accumulate (for small correction terms)
__device__ __forceinline__ void mma16816h(uint32_t* d, const uint32_t* a,
                                          const uint32_t* b) {
    asm volatile(
        "mma.sync.aligned.m16n8k16.row.col.f16.f16.f16.f16 "
        "{%0,%1}, {%2,%3,%4,%5}, {%6,%7}, {%0,%1};"
        : "+r"(d[0]), "+r"(d[1])
        : "r"(a[0]), "r"(a[1]), "r"(a[2]), "r"(a[3]), "r"(b[0]), "r"(b[1]));
}

// ---------------------------------------------------------------------------
// hi/lo fp16 split and fp16 convert
// ---------------------------------------------------------------------------
__global__ void split_kernel(const float* __restrict__ in,
                             __half* __restrict__ hi,
                             __half* __restrict__ lo, int n) {
    int i = blockIdx.x * blockDim.x + threadIdx.x;
    int stride = gridDim.x * blockDim.x;
    for (; i < n; i += stride) {
        float v = in[i];
        __half h = __float2half(v);
        hi[i] = h;
        lo[i] = __float2half(v - __half2float(h));
    }
}

__global__ void cvt_kernel(const float* __restrict__ in,
                           __half* __restrict__ out, int n) {
    int i = blockIdx.x * blockDim.x + threadIdx.x;
    int stride = gridDim.x * blockDim.x;
    for (; i < n; i += stride) out[i] = __float2half(in[i]);
}

__global__ void init_state_kernel() {
    int i = blockIdx.x * blockDim.x + threadIdx.x;
    if (i < BB * HH) {
        __half z = __float2half(0.f);
        g_h[0][i] = z; g_h[1][i] = z;
    }
    if (i < 2 * TT) g_ctr[i] = 0;
}

// ---------------------------------------------------------------------------
// Tensor-core input GEMM: XG = Ahi*W [f32-acc] + Alo*W [f16-acc] + b1 + b2.
// fp16 2-pass, R4 fragment layout. Pass 2 uses half-precision accumulators
// (correction term magnitude ~3e-4 of gates — f16-safe).
// ---------------------------------------------------------------------------
#define PAD 40
#define NCH 64   // 2 passes * 32 chunks

__global__ __launch_bounds__(256)
void gemm_mma_kernel(const __half* __restrict__ Ahi,
                     const __half* __restrict__ Alo,
                     const __half* __restrict__ W,
                     const float* __restrict__ b1,
                     const float* __restrict__ b2,
                     float* __restrict__ XG) {
    __shared__ __half As[2][128 * PAD];
    __shared__ __half Bs[2][128 * PAD];

    const int tid  = threadIdx.x;
    const int wid  = tid >> 5;
    const int lane = tid & 31;
    const int m0 = blockIdx.y * 128;
    const int n0 = blockIdx.x * 128;
    const int wm = (wid & 3) * 32;
    const int wn = (wid >> 2) * 64;

    float acc[2][8][4];
    uint32_t acch[2][8][2];
#pragma unroll
    for (int i = 0; i < 2; i++)
#pragma unroll
        for (int j = 0; j < 8; j++) {
#pragma unroll
            for (int q = 0; q < 4; q++) acc[i][j][q] = 0.f;
            acch[i][j][0] = 0u; acch[i][j][1] = 0u;
        }

    const int srow  = tid >> 1;
    const int skoff = (tid & 1) * 16;
    const uint32_t as_base = smem_u32(As);
    const uint32_t bs_base = smem_u32(Bs);

    const int a_r = lane & 15;
    const int a_c = (lane >> 4) * 8;
    const int b_r = ((lane >> 4) * 8) + (lane & 7);
    const int b_c = ((lane >> 3) & 1) * 8;

    {
        const uint4* a4 = (const uint4*)(Ahi + (size_t)(m0 + srow) * HH + skoff);
        const uint4* b4 = (const uint4*)(W + (size_t)(n0 + srow) * HH + skoff);
        uint4 av0 = a4[0], av1 = a4[1];
        uint4 bv0 = b4[0], bv1 = b4[1];
        *(uint4*)&As[0][srow * PAD + skoff]     = av0;
        *(uint4*)&As[0][srow * PAD + skoff + 8] = av1;
        *(uint4*)&Bs[0][srow * PAD + skoff]     = bv0;
        *(uint4*)&Bs[0][srow * PAD + skoff + 8] = bv1;
    }
    __syncthreads();

    for (int c = 0; c < NCH; c++) {
        const int buf = c & 1;
        uint4 av0, av1, bv0, bv1;
        if (c + 1 < NCH) {
            const int cn  = c + 1;
            const int ph  = cn >> 5;
            const int kk0 = (cn & 31) * 32;
            const __half* Ap = (ph == 1 ? Alo : Ahi);
            const uint4* a4 = (const uint4*)(Ap + (size_t)(m0 + srow) * HH + kk0 + skoff);
            const uint4* b4 = (const uint4*)(W + (size_t)(n0 + srow) * HH + kk0 + skoff);
            av0 = a4[0]; av1 = a4[1];
            bv0 = b4[0]; bv1 = b4[1];
        }

        const bool hiPass = (c < 32);
#pragma unroll
        for (int kk = 0; kk < 2; kk++) {
            uint32_t afrag[2][4];
#pragma unroll
            for (int fm = 0; fm < 2; fm++) {
                const int row = wm + fm * 16 + a_r;
                const int col = kk * 16 + a_c;
                ldsm4(afrag[fm], as_base + (buf * 128 * PAD + row * PAD + col) * 2);
            }
            uint32_t bfrag[8][2];
#pragma unroll
            for (int fp = 0; fp < 4; fp++) {
                uint32_t r[4];
                const int row = wn + fp * 16 + b_r;
                const int col = kk * 16 + b_c;
                ldsm4(r, bs_base + (buf * 128 * PAD + row * PAD + col) * 2);
                bfrag[fp * 2][0]     = r[0];
                bfrag[fp * 2][1]     = r[1];
                bfrag[fp * 2 + 1][0] = r[2];
                bfrag[fp * 2 + 1][1] = r[3];
            }
            if (hiPass) {
#pragma unroll
                for (int fm = 0; fm < 2; fm++)
#pragma unroll
                    for (int fn = 0; fn < 8; fn++)
                        mma16816(acc[fm][fn], afrag[fm], bfrag[fn]);
            } else {
#pragma unroll
                for (int fm = 0; fm < 2; fm++)
#pragma unroll
                    for (int fn = 0; fn < 8; fn++)
                        mma16816h(acch[fm][fn], afrag[fm], bfrag[fn]);
            }
        }

        if (c + 1 < NCH) {
            const int nb = buf ^ 1;
            *(uint4*)&As[nb][srow * PAD + skoff]     = av0;
            *(uint4*)&As[nb][srow * PAD + skoff + 8] = av1;
            *(uint4*)&Bs[nb][srow * PAD + skoff]     = bv0;
            *(uint4*)&Bs[nb][srow * PAD + skoff + 8] = bv1;
        }
        __syncthreads();
    }

    const int er = lane >> 2;
    const int ec = (lane & 3) * 2;
#pragma unroll
    for (int fm = 0; fm < 2; fm++) {
#pragma unroll
        for (int fn = 0; fn < 8; fn++) {
            const int row = m0 + wm + fm * 16 + er;
            const int col = n0 + wn + fn * 8 + ec;
            const float bs0 = b1[col] + b2[col];
            const float bs1 = b1[col + 1] + b2[col + 1];
            __half2 q0 = *(__half2*)&acch[fm][fn][0];
            __half2 q1 = *(__half2*)&acch[fm][fn][1];
            float* p0 = XG + (size_t)row * G4 + col;
            float* p1 = XG + (size_t)(row + 8) * G4 + col;
            p0[0] = acc[fm][fn][0] + __half2float(q0.x) + bs0;
            p0[1] = acc[fm][fn][1] + __half2float(q0.y) + bs1;
            p1[0] = acc[fm][fn][2] + __half2float(q1.x) + bs0;
            p1[1] = acc[fm][fn][3] + __half2float(q1.y) + bs1;
        }
    }
}

// ---------------------------------------------------------------------------
// Persistent LSTM layer kernel v6: single-fp16 h, single-fp16 W.
// gates = h*W [f32-acc, even/odd ILP chains]. 64 f32-acc mma per warp/step.
// 128 CTAs x 512 threads; CTA jb owns 8 h-cols -> 32 gate rows; warp m16 x n8;
// W resident in smem; k-chunk 128; release/acquire step barrier with
// out-store + next-xg prefetch + fused next-layer hi/lo split off-path.
// ---------------------------------------------------------------------------
#define PADW 1032
#define PADA 136
#define OFF_W   0
#define OFF_A   (32 * PADW)
#define ATILE(buf) (OFF_A + (buf) * (64 * PADA))
#define OFF_GS_B ((OFF_A + 2 * 64 * PADA) * 2)
#define PSMEM    (OFF_GS_B + 64 * 33 * 4)      // ~109 KB

__global__ __launch_bounds__(512)
void lstm_persistent(const float* __restrict__ xg,
                     const __half* __restrict__ W,
                     const float* __restrict__ res,
                     float* __restrict__ outp,
                     __half* __restrict__ h,        // [2][B*H]
                     __half* __restrict__ anext_hi, // fused split out (or null)
                     __half* __restrict__ anext_lo,
                     int* __restrict__ ctr)
{
    extern __shared__ __align__(16) __half smh[];
    float* gs = (float*)((char*)smh + OFF_GS_B);

    const int tid  = threadIdx.x;
    const int wid  = tid >> 5;
    const int lane = tid & 31;
    const int jb   = blockIdx.x;
    const int wm   = (wid & 3) * 16;    // batch offset
    const int wn   = (wid >> 2) * 8;    // gate-col offset

    const uint32_t smb = smem_u32(smh);
    const int a_r = lane & 15;
    const int a_c = (lane >> 4) * 8;
    const int w_r = lane & 7;
    const int w_c = ((lane >> 3) & 1) * 8;

    // ---- load W tile into smem (once) ----
#pragma unroll
    for (int i = 0; i < 8; i++) {
        const int idx = tid + i * 512;
        const int row = idx >> 7;
        const int seg = (idx & 127) * 8;
        const size_t grow = (size_t)((row >> 3) * HH + jb * 8 + (row & 7)) * HH + seg;
        *(uint4*)&smh[OFF_W + row * PADW + seg] = *(const uint4*)(W + grow);
    }
    __syncthreads();

    // pointwise mapping (fixed across steps)
    const int pb = tid >> 3;
    const int pj = tid & 7;
    const size_t ho = (size_t)pb * HH + jb * 8 + pj;
    const size_t xb = (size_t)pb * G4 + jb * 8 + pj;
    float creg = 0.f;

    // prefetch step-0 pointwise inputs
    float xi = __ldg(xg + xb);
    float xf = __ldg(xg + xb + HH);
    float xq = __ldg(xg + xb + 2 * HH);
    float xo = __ldg(xg + xb + 3 * HH);
    float rv = __ldg(res + ho);

    for (int t = 0; t < TT; t++) {
        const int pin  = t & 1;
        const __half* hin = h + pin * (BB * HH);
        float* out_t = outp + (size_t)t * BB * HH;

        float accA[4], accB[4];
        accA[0] = accA[1] = accA[2] = accA[3] = 0.f;
        accB[0] = accB[1] = accB[2] = accB[3] = 0.f;

        // stage chunk 0: 64 rows x 128 halfwords = 1024 uint4, 2 per thread
#pragma unroll
        for (int i = 0; i < 2; i++) {
            const int idx = tid + i * 512;
            const int row = idx >> 4;
            const int seg = (idx & 15) * 8;
            uint4 v = __ldcg((const uint4*)(hin + (size_t)row * HH + seg));
            *(uint4*)&smh[ATILE(0) + row * PADA + seg] = v;
        }
        __syncthreads();

        for (int ch = 0; ch < 8; ch++) {
            const int buf = ch & 1;
            uint4 pf[2];
            if (ch + 1 < 8) {
                const int k0 = (ch + 1) * 128;
#pragma unroll
                for (int i = 0; i < 2; i++) {
                    const int idx = tid + i * 512;
                    const int row = idx >> 4;
                    const int seg = (idx & 15) * 8;
                    pf[i] = __ldcg((const uint4*)(hin + (size_t)row * HH + k0 + seg));
                }
            }

#pragma unroll
            for (int kk = 0; kk < 8; kk++) {
                uint32_t ah[4];
                ldsm4(ah, smb + (ATILE(buf) + (wm + a_r) * PADA + kk * 16 + a_c) * 2);
                const int wcol = ch * 128 + kk * 16 + w_c;
                uint32_t bw[2];
                ldsm2(bw, smb + (OFF_W + (wn + w_r) * PADW + wcol) * 2);
                if (kk & 1) mma16816(accB, ah, bw);
                else        mma16816(accA, ah, bw);
            }

            if (ch + 1 < 8) {
                const int nb = buf ^ 1;
#pragma unroll
                for (int i = 0; i < 2; i++) {
                    const int idx = tid + i * 512;
                    const int row = idx >> 4;
                    const int seg = (idx & 15) * 8;
                    *(uint4*)&smh[ATILE(nb) + row * PADA + seg] = pf[i];
                }
            }
            __syncthreads();
        }

        // acc -> gs  (warp m16 x n8)
        {
            const int er = lane >> 2;
            const int ec = (lane & 3) * 2;
            gs[(wm + er) * 33 + wn + ec]         = accA[0] + accB[0];
            gs[(wm + er) * 33 + wn + ec + 1]     = accA[1] + accB[1];
            gs[(wm + er + 8) * 33 + wn + ec]     = accA[2] + accB[2];
            gs[(wm + er + 8) * 33 + wn + ec + 1] = accA[3] + accB[3];
        }
        __syncthreads();

        // fused pointwise: 1 (b, jj) pair per thread
        float ov;
        {
            float i_ = gs[pb * 33 +      pj] + xi;
            float f_ = gs[pb * 33 +  8 + pj] + xf;
            float q_ = gs[pb * 33 + 16 + pj] + xq;
            float o_ = gs[pb * 33 + 24 + pj] + xo;

            i_ = 1.f / (1.f + __expf(-i_));
            f_ = 1.f / (1.f + __expf(-f_));
            q_ = tanhf(q_);
            o_ = 1.f / (1.f + __expf(-o_));

            creg = f_ * creg + i_ * q_;
            const float hv = o_ * tanhf(creg);
            ov = hv + rv;

            const int pout = pin ^ 1;
            h[pout * (BB * HH) + ho] = __float2half(hv);
        }

        // ---- publish h, then step barrier (release/acquire) ----
        __syncthreads();
        if (tid == 0)
            asm volatile("red.release.gpu.global.add.s32 [%0], 1;"
                         :: "l"(ctr + t) : "memory");

        // off-critical-path: residual out + fused next-layer split + prefetch
        out_t[ho] = ov;
        if (anext_hi) {
            const size_t tofs = (size_t)t * BB * HH + ho;
            __half oh = __float2half(ov);
            anext_hi[tofs] = oh;
            anext_lo[tofs] = __float2half(ov - __half2float(oh));
        }
        if (t + 1 < TT) {
            const float* xg_n  = xg + (size_t)(t + 1) * BB * G4;
            xi = __ldg(xg_n + xb);
            xf = __ldg(xg_n + xb + HH);
            xq = __ldg(xg_n + xb + 2 * HH);
            xo = __ldg(xg_n + xb + 3 * HH);
            rv = __ldg(res + (size_t)(t + 1) * BB * HH + ho);

            if (tid == 0) {
                int v;
                do {
                    asm volatile("ld.acquire.gpu.global.s32 %0, [%1];"
                                 : "=r"(v) : "l"(ctr + t) : "memory");
                    if (v < NCT) __nanosleep(32);
                } while (v < NCT);
            }
            __syncthreads();
        }
    }
}

// ---------------------------------------------------------------------------
// Host launch
// ---------------------------------------------------------------------------
extern "C" void kernel_launch(void* const* d_in, const int* in_sizes, int n_in,
                              void* d_out, int out_size)
{
    (void)in_sizes; (void)n_in; (void)out_size;
    const float* x     = (const float*)d_in[0];
    const float* w_ih5 = (const float*)d_in[1];
    const float* w_hh5 = (const float*)d_in[2];
    const float* b_ih5 = (const float*)d_in[3];
    const float* b_hh5 = (const float*)d_in[4];
    const float* w_ih6 = (const float*)d_in[5];
    const float* w_hh6 = (const float*)d_in[6];
    const float* b_ih6 = (const float*)d_in[7];
    const float* b_hh6 = (const float*)d_in[8];
    float* out = (float*)d_out;

    float *xg, *out5;
    __half *ahi, *alo, *w5, *w6, *u5, *u6, *hbuf;
    int* ctr;
    cudaGetSymbolAddress((void**)&xg,   g_xg);
    cudaGetSymbolAddress((void**)&out5, g_out5);
    cudaGetSymbolAddress((void**)&ahi,  g_ahi);
    cudaGetSymbolAddress((void**)&alo,  g_alo);
    cudaGetSymbolAddress((void**)&w5,   g_w5);
    cudaGetSymbolAddress((void**)&w6,   g_w6);
    cudaGetSymbolAddress((void**)&u5,   g_u5);
    cudaGetSymbolAddress((void**)&u6,   g_u6);
    cudaGetSymbolAddress((void**)&hbuf, g_h);
    cudaGetSymbolAddress((void**)&ctr,  g_ctr);

    cudaFuncSetAttribute(lstm_persistent,
                         cudaFuncAttributeMaxDynamicSharedMemorySize, PSMEM);

    const dim3 gemm_grid(G4 / 128, MM / 128);

    // weight prep (fp16 converts)
    cvt_kernel<<<4096, 256>>>(w_ih5, w5, G4 * HH);
    cvt_kernel<<<4096, 256>>>(w_ih6, w6, G4 * HH);
    cvt_kernel<<<4096, 256>>>(w_hh5, u5, G4 * HH);
    cvt_kernel<<<4096, 256>>>(w_hh6, u6, G4 * HH);

    // ---- Layer 5 ----
    split_kernel<<<8192, 256>>>(x, ahi, alo, MM * HH);
    init_state_kernel<<<64, 1024>>>();
    gemm_mma_kernel<<<gemm_grid, 256>>>(ahi, alo, w5, b_ih5, b_hh5, xg);
    // persistent layer 5 also emits the hi/lo split of out5 for layer 6's GEMM
    lstm_persistent<<<NCT, 512, PSMEM>>>(xg, u5, x, out5, hbuf,
                                         ahi, alo, ctr);

    // ---- Layer 6 ----
    init_state_kernel<<<64, 1024>>>();
    gemm_mma_kernel<<<gemm_grid, 256>>>(ahi, alo, w6, b_ih6, b_hh6, xg);
    lstm_persistent<<<NCT, 512, PSMEM>>>(xg, u6, out5, out, hbuf,
                                         ((__half*)0), ((__half*)0), ctr + TT);
}

// round 17
// speedup vs baseline: 1.2632x; 1.2632x over previous
#include <cuda_runtime.h>
#include <cuda_fp16.h>
#include <math.h>
#include <stdint.h>

#define TT 256
#define BB 64
#define HH 1024
#define G4 4096
#define MM (TT*BB)
#define NCT 128           // CTAs in persistent step kernel

// ---------------------------------------------------------------------------
// Scratch (device globals: allocation-free per harness rules)
// ---------------------------------------------------------------------------
__device__ float g_xg[(size_t)MM * G4];
__device__ float g_out5[(size_t)MM * HH];
__device__ __half g_h[2][BB * HH];          // ping-pong hidden (fp16)
__device__ __half g_a[(size_t)MM * HH];     // activations fp16 (GEMM A)
__device__ __half g_w5[(size_t)G4 * HH];    // w_ih5 fp16
__device__ __half g_w6[(size_t)G4 * HH];    // w_ih6 fp16
__device__ __half g_u5[(size_t)G4 * HH];    // w_hh5 fp16
__device__ __half g_u6[(size_t)G4 * HH];    // w_hh6 fp16
__device__ int g_ctr[2 * TT];

// ---------------------------------------------------------------------------
// mma.sync helpers
// ---------------------------------------------------------------------------
__device__ __forceinline__ uint32_t smem_u32(const void* p) {
    uint32_t a;
    asm("{ .reg .u64 t; cvta.to.shared.u64 t, %1; cvt.u32.u64 %0, t; }"
        : "=r"(a) : "l"(p));
    return a;
}
__device__ __forceinline__ void ldsm4(uint32_t* r, uint32_t addr) {
    asm volatile("ldmatrix.sync.aligned.m8n8.x4.shared.b16 {%0,%1,%2,%3}, [%4];"
                 : "=r"(r[0]), "=r"(r[1]), "=r"(r[2]), "=r"(r[3]) : "r"(addr));
}
__device__ __forceinline__ void ldsm2(uint32_t* r, uint32_t addr) {
    asm volatile("ldmatrix.sync.aligned.m8n8.x2.shared.b16 {%0,%1}, [%2];"
                 : "=r"(r[0]), "=r"(r[1]) : "r"(addr));
}
// fp16 inputs, fp32 accumulate
__device__ __forceinline__ void mma16816(float* d, const uint32_t* a,
                                         const uint32_t* b) {
    asm volatile(
        "mma.sync.aligned.m16n8k16.row.col.f32.f16.f16.f32 "
        "{%0,%1,%2,%3}, {%4,%5,%6,%7}, {%8,%9}, {%0,%1,%2,%3};"
        : "+f"(d[0]), "+f"(d[1]), "+f"(d[2]), "+f"(d[3])
        : "r"(a[0]), "r"(a[1]), "r"(a[2]), "r"(a[3]), "r"(b[0]), "r"(b[1]));
}

// ---------------------------------------------------------------------------
// fp16 convert
// ---------------------------------------------------------------------------
__global__ void cvt_kernel(const float* __restrict__ in,
                           __half* __restrict__ out, int n) {
    int i = blockIdx.x * blockDim.x + threadIdx.x;
    int stride = gridDim.x * blockDim.x;
    for (; i < n; i += stride) out[i] = __float2half(in[i]);
}

__global__ void init_state_kernel() {
    int i = blockIdx.x * blockDim.x + threadIdx.x;
    if (i < BB * HH) {
        __half z = __float2half(0.f);
        g_h[0][i] = z; g_h[1][i] = z;
    }
    if (i < 2 * TT) g_ctr[i] = 0;
}

// ---------------------------------------------------------------------------
// Tensor-core input GEMM (single fp16 pass, f32 acc, R4 fragment layout):
// XG[m][n] = sum_k A[m][k] W[n][k] + b1[n] + b2[n]
// ---------------------------------------------------------------------------
#define PAD 40
#define NCH 32

__global__ __launch_bounds__(256)
void gemm_mma_kernel(const __half* __restrict__ A,
                     const __half* __restrict__ W,
                     const float* __restrict__ b1,
                     const float* __restrict__ b2,
                     float* __restrict__ XG) {
    __shared__ __half As[2][128 * PAD];
    __shared__ __half Bs[2][128 * PAD];

    const int tid  = threadIdx.x;
    const int wid  = tid >> 5;
    const int lane = tid & 31;
    const int m0 = blockIdx.y * 128;
    const int n0 = blockIdx.x * 128;
    const int wm = (wid & 3) * 32;
    const int wn = (wid >> 2) * 64;

    float acc[2][8][4];
#pragma unroll
    for (int i = 0; i < 2; i++)
#pragma unroll
        for (int j = 0; j < 8; j++)
#pragma unroll
            for (int q = 0; q < 4; q++) acc[i][j][q] = 0.f;

    const int srow  = tid >> 1;
    const int skoff = (tid & 1) * 16;
    const uint32_t as_base = smem_u32(As);
    const uint32_t bs_base = smem_u32(Bs);

    const int a_r = lane & 15;
    const int a_c = (lane >> 4) * 8;
    const int b_r = ((lane >> 4) * 8) + (lane & 7);
    const int b_c = ((lane >> 3) & 1) * 8;

    {
        const uint4* a4 = (const uint4*)(A + (size_t)(m0 + srow) * HH + skoff);
        const uint4* b4 = (const uint4*)(W + (size_t)(n0 + srow) * HH + skoff);
        uint4 av0 = a4[0], av1 = a4[1];
        uint4 bv0 = b4[0], bv1 = b4[1];
        *(uint4*)&As[0][srow * PAD + skoff]     = av0;
        *(uint4*)&As[0][srow * PAD + skoff + 8] = av1;
        *(uint4*)&Bs[0][srow * PAD + skoff]     = bv0;
        *(uint4*)&Bs[0][srow * PAD + skoff + 8] = bv1;
    }
    __syncthreads();

    for (int c = 0; c < NCH; c++) {
        const int buf = c & 1;
        uint4 av0, av1, bv0, bv1;
        if (c + 1 < NCH) {
            const int kk0 = (c + 1) * 32;
            const uint4* a4 = (const uint4*)(A + (size_t)(m0 + srow) * HH + kk0 + skoff);
            const uint4* b4 = (const uint4*)(W + (size_t)(n0 + srow) * HH + kk0 + skoff);
            av0 = a4[0]; av1 = a4[1];
            bv0 = b4[0]; bv1 = b4[1];
        }

#pragma unroll
        for (int kk = 0; kk < 2; kk++) {
            uint32_t afrag[2][4];
#pragma unroll
            for (int fm = 0; fm < 2; fm++) {
                const int row = wm + fm * 16 + a_r;
                const int col = kk * 16 + a_c;
                ldsm4(afrag[fm], as_base + (buf * 128 * PAD + row * PAD + col) * 2);
            }
            uint32_t bfrag[8][2];
#pragma unroll
            for (int fp = 0; fp < 4; fp++) {
                uint32_t r[4];
                const int row = wn + fp * 16 + b_r;
                const int col = kk * 16 + b_c;
                ldsm4(r, bs_base + (buf * 128 * PAD + row * PAD + col) * 2);
                bfrag[fp * 2][0]     = r[0];
                bfrag[fp * 2][1]     = r[1];
                bfrag[fp * 2 + 1][0] = r[2];
                bfrag[fp * 2 + 1][1] = r[3];
            }
#pragma unroll
            for (int fm = 0; fm < 2; fm++)
#pragma unroll
                for (int fn = 0; fn < 8; fn++)
                    mma16816(acc[fm][fn], afrag[fm], bfrag[fn]);
        }

        if (c + 1 < NCH) {
            const int nb = buf ^ 1;
            *(uint4*)&As[nb][srow * PAD + skoff]     = av0;
            *(uint4*)&As[nb][srow * PAD + skoff + 8] = av1;
            *(uint4*)&Bs[nb][srow * PAD + skoff]     = bv0;
            *(uint4*)&Bs[nb][srow * PAD + skoff + 8] = bv1;
        }
        __syncthreads();
    }

    const int er = lane >> 2;
    const int ec = (lane & 3) * 2;
#pragma unroll
    for (int fm = 0; fm < 2; fm++) {
#pragma unroll
        for (int fn = 0; fn < 8; fn++) {
            const int row = m0 + wm + fm * 16 + er;
            const int col = n0 + wn + fn * 8 + ec;
            const float bs0 = b1[col] + b2[col];
            const float bs1 = b1[col + 1] + b2[col + 1];
            float* p0 = XG + (size_t)row * G4 + col;
            float* p1 = XG + (size_t)(row + 8) * G4 + col;
            p0[0] = acc[fm][fn][0] + bs0;
            p0[1] = acc[fm][fn][1] + bs1;
            p1[0] = acc[fm][fn][2] + bs0;
            p1[1] = acc[fm][fn][3] + bs1;
        }
    }
}

// ---------------------------------------------------------------------------
// Persistent LSTM layer kernel v7: single-fp16 h and W, k-chunk 256
// (4 chunks, 4 syncs). gates = h*W [f32-acc, even/odd ILP chains].
// 128 CTAs x 512 threads; CTA jb owns 8 h-cols -> 32 gate rows; warp m16 x n8;
// W resident in smem; release/acquire step barrier with out-store +
// next-xg prefetch + fused next-layer fp16 convert off-path.
// ---------------------------------------------------------------------------
#define PADW 1032
#define PADA 264
#define OFF_W   0
#define OFF_A   (32 * PADW)
#define ATILE(buf) (OFF_A + (buf) * (64 * PADA))
#define OFF_GS_B ((OFF_A + 2 * 64 * PADA) * 2)
#define PSMEM    (OFF_GS_B + 64 * 33 * 4)      // ~142 KB

__global__ __launch_bounds__(512)
void lstm_persistent(const float* __restrict__ xg,
                     const __half* __restrict__ W,
                     const float* __restrict__ res,
                     float* __restrict__ outp,
                     __half* __restrict__ h,        // [2][B*H]
                     __half* __restrict__ anext,    // fused cvt out (or null)
                     int* __restrict__ ctr)
{
    extern __shared__ __align__(16) __half smh[];
    float* gs = (float*)((char*)smh + OFF_GS_B);

    const int tid  = threadIdx.x;
    const int wid  = tid >> 5;
    const int lane = tid & 31;
    const int jb   = blockIdx.x;
    const int wm   = (wid & 3) * 16;    // batch offset
    const int wn   = (wid >> 2) * 8;    // gate-col offset

    const uint32_t smb = smem_u32(smh);
    const int a_r = lane & 15;
    const int a_c = (lane >> 4) * 8;
    const int w_r = lane & 7;
    const int w_c = ((lane >> 3) & 1) * 8;

    // ---- load W tile into smem (once) ----
#pragma unroll
    for (int i = 0; i < 8; i++) {
        const int idx = tid + i * 512;
        const int row = idx >> 7;
        const int seg = (idx & 127) * 8;
        const size_t grow = (size_t)((row >> 3) * HH + jb * 8 + (row & 7)) * HH + seg;
        *(uint4*)&smh[OFF_W + row * PADW + seg] = *(const uint4*)(W + grow);
    }
    __syncthreads();

    // pointwise mapping (fixed across steps)
    const int pb = tid >> 3;
    const int pj = tid & 7;
    const size_t ho = (size_t)pb * HH + jb * 8 + pj;
    const size_t xb = (size_t)pb * G4 + jb * 8 + pj;
    float creg = 0.f;

    // prefetch step-0 pointwise inputs
    float xi = __ldg(xg + xb);
    float xf = __ldg(xg + xb + HH);
    float xq = __ldg(xg + xb + 2 * HH);
    float xo = __ldg(xg + xb + 3 * HH);
    float rv = __ldg(res + ho);

    for (int t = 0; t < TT; t++) {
        const int pin  = t & 1;
        const __half* hin = h + pin * (BB * HH);
        float* out_t = outp + (size_t)t * BB * HH;

        float accA[4], accB[4];
        accA[0] = accA[1] = accA[2] = accA[3] = 0.f;
        accB[0] = accB[1] = accB[2] = accB[3] = 0.f;

        // stage chunk 0: 64 rows x 256 halfwords = 2048 uint4, 4 per thread
#pragma unroll
        for (int i = 0; i < 4; i++) {
            const int idx = tid + i * 512;
            const int row = idx >> 5;
            const int seg = (idx & 31) * 8;
            uint4 v = __ldcg((const uint4*)(hin + (size_t)row * HH + seg));
            *(uint4*)&smh[ATILE(0) + row * PADA + seg] = v;
        }
        __syncthreads();

        for (int ch = 0; ch < 4; ch++) {
            const int buf = ch & 1;
            uint4 pf[4];
            if (ch + 1 < 4) {
                const int k0 = (ch + 1) * 256;
#pragma unroll
                for (int i = 0; i < 4; i++) {
                    const int idx = tid + i * 512;
                    const int row = idx >> 5;
                    const int seg = (idx & 31) * 8;
                    pf[i] = __ldcg((const uint4*)(hin + (size_t)row * HH + k0 + seg));
                }
            }

#pragma unroll
            for (int kk = 0; kk < 16; kk++) {
                uint32_t ah[4];
                ldsm4(ah, smb + (ATILE(buf) + (wm + a_r) * PADA + kk * 16 + a_c) * 2);
                const int wcol = ch * 256 + kk * 16 + w_c;
                uint32_t bw[2];
                ldsm2(bw, smb + (OFF_W + (wn + w_r) * PADW + wcol) * 2);
                if (kk & 1) mma16816(accB, ah, bw);
                else        mma16816(accA, ah, bw);
            }

            if (ch + 1 < 4) {
                const int nb = buf ^ 1;
#pragma unroll
                for (int i = 0; i < 4; i++) {
                    const int idx = tid + i * 512;
                    const int row = idx >> 5;
                    const int seg = (idx & 31) * 8;
                    *(uint4*)&smh[ATILE(nb) + row * PADA + seg] = pf[i];
                }
            }
            __syncthreads();
        }

        // acc -> gs  (warp m16 x n8)
        {
            const int er = lane >> 2;
            const int ec = (lane & 3) * 2;
            gs[(wm + er) * 33 + wn + ec]         = accA[0] + accB[0];
            gs[(wm + er) * 33 + wn + ec + 1]     = accA[1] + accB[1];
            gs[(wm + er + 8) * 33 + wn + ec]     = accA[2] + accB[2];
            gs[(wm + er + 8) * 33 + wn + ec + 1] = accA[3] + accB[3];
        }
        __syncthreads();

        // fused pointwise: 1 (b, jj) pair per thread
        float ov;
        {
            float i_ = gs[pb * 33 +      pj] + xi;
            float f_ = gs[pb * 33 +  8 + pj] + xf;
            float q_ = gs[pb * 33 + 16 + pj] + xq;
            float o_ = gs[pb * 33 + 24 + pj] + xo;

            i_ = 1.f / (1.f + __expf(-i_));
            f_ = 1.f / (1.f + __expf(-f_));
            q_ = tanhf(q_);
            o_ = 1.f / (1.f + __expf(-o_));

            creg = f_ * creg + i_ * q_;
            const float hv = o_ * tanhf(creg);
            ov = hv + rv;

            const int pout = pin ^ 1;
            h[pout * (BB * HH) + ho] = __float2half(hv);
        }

        // ---- publish h, then step barrier (release/acquire) ----
        __syncthreads();
        if (tid == 0)
            asm volatile("red.release.gpu.global.add.s32 [%0], 1;"
                         :: "l"(ctr + t) : "memory");

        // off-critical-path: residual out + fused next-layer cvt + prefetch
        out_t[ho] = ov;
        if (anext) {
            anext[(size_t)t * BB * HH + ho] = __float2half(ov);
        }
        if (t + 1 < TT) {
            const float* xg_n  = xg + (size_t)(t + 1) * BB * G4;
            xi = __ldg(xg_n + xb);
            xf = __ldg(xg_n + xb + HH);
            xq = __ldg(xg_n + xb + 2 * HH);
            xo = __ldg(xg_n + xb + 3 * HH);
            rv = __ldg(res + (size_t)(t + 1) * BB * HH + ho);

            if (tid == 0) {
                int v;
                do {
                    asm volatile("ld.acquire.gpu.global.s32 %0, [%1];"
                                 : "=r"(v) : "l"(ctr + t) : "memory");
                    if (v < NCT) __nanosleep(32);
                } while (v < NCT);
            }
            __syncthreads();
        }
    }
}

// ---------------------------------------------------------------------------
// Host launch
// ---------------------------------------------------------------------------
extern "C" void kernel_launch(void* const* d_in, const int* in_sizes, int n_in,
                              void* d_out, int out_size)
{
    (void)in_sizes; (void)n_in; (void)out_size;
    const float* x     = (const float*)d_in[0];
    const float* w_ih5 = (const float*)d_in[1];
    const float* w_hh5 = (const float*)d_in[2];
    const float* b_ih5 = (const float*)d_in[3];
    const float* b_hh5 = (const float*)d_in[4];
    const float* w_ih6 = (const float*)d_in[5];
    const float* w_hh6 = (const float*)d_in[6];
    const float* b_ih6 = (const float*)d_in[7];
    const float* b_hh6 = (const float*)d_in[8];
    float* out = (float*)d_out;

    float *xg, *out5;
    __half *a, *w5, *w6, *u5, *u6, *hbuf;
    int* ctr;
    cudaGetSymbolAddress((void**)&xg,   g_xg);
    cudaGetSymbolAddress((void**)&out5, g_out5);
    cudaGetSymbolAddress((void**)&a,    g_a);
    cudaGetSymbolAddress((void**)&w5,   g_w5);
    cudaGetSymbolAddress((void**)&w6,   g_w6);
    cudaGetSymbolAddress((void**)&u5,   g_u5);
    cudaGetSymbolAddress((void**)&u6,   g_u6);
    cudaGetSymbolAddress((void**)&hbuf, g_h);
    cudaGetSymbolAddress((void**)&ctr,  g_ctr);

    cudaFuncSetAttribute(lstm_persistent,
                         cudaFuncAttributeMaxDynamicSharedMemorySize, PSMEM);

    const dim3 gemm_grid(G4 / 128, MM / 128);

    // weight prep (fp16 converts)
    cvt_kernel<<<4096, 256>>>(w_ih5, w5, G4 * HH);
    cvt_kernel<<<4096, 256>>>(w_ih6, w6, G4 * HH);
    cvt_kernel<<<4096, 256>>>(w_hh5, u5, G4 * HH);
    cvt_kernel<<<4096, 256>>>(w_hh6, u6, G4 * HH);

    // ---- Layer 5 ----
    cvt_kernel<<<8192, 256>>>(x, a, MM * HH);
    init_state_kernel<<<64, 1024>>>();
    gemm_mma_kernel<<<gemm_grid, 256>>>(a, w5, b_ih5, b_hh5, xg);
    // persistent layer 5 also emits fp16(out5) as layer-6 GEMM input
    lstm_persistent<<<NCT, 512, PSMEM>>>(xg, u5, x, out5, hbuf, a, ctr);

    // ---- Layer 6 ----
    init_state_kernel<<<64, 1024>>>();
    gemm_mma_kernel<<<gemm_grid, 256>>>(a, w6, b_ih6, b_hh6, xg);
    lstm_persistent<<<NCT, 512, PSMEM>>>(xg, u6, out5, out, hbuf,
                                         ((__half*)0), ctr + TT);
}